// round 16
// baseline (speedup 1.0000x reference)
#include <cuda_runtime.h>
#include <cuda_bf16.h>
#include <mma.h>
#include <math.h>
#include <stdint.h>

using namespace nvcuda;

// ---------------- problem constants ----------------
#define NTOK   4096            // B*S
#define HIDDIM 2048
#define QLR    1536
#define KVLR   512
#define HEADS  16
#define NOPE   128
#define ROPED  64
#define HD     192             // NOPE+ROPE
#define VDIM   128
#define SEQ    1024
#define BATCH  4
#define QDIM   (HEADS*HD)      // 3072
#define KVDIM  (KVLR+ROPED)    // 576
#define QAKV_N 2176            // QLR + KVDIM padded to x128
#define QAKV_V 2112
#define KNOPE_DIM (HEADS*NOPE) // 2048
#define VVDIM  (HEADS*VDIM)    // 2048
#define KV2_N  4096            // knope | v

// ---------------- fp32 scratch ----------------
__device__ float g_qakv [(size_t)NTOK*QAKV_N];
__device__ float g_q    [(size_t)NTOK*QDIM];

// ---------------- bf16 hi/lo scratch ----------------
__device__ __align__(16) __nv_bfloat16 g_x_hi  [(size_t)NTOK*HIDDIM];
__device__ __align__(16) __nv_bfloat16 g_x_lo  [(size_t)NTOK*HIDDIM];
__device__ __align__(16) __nv_bfloat16 g_qn_hi [(size_t)NTOK*QLR];
__device__ __align__(16) __nv_bfloat16 g_qn_lo [(size_t)NTOK*QLR];
__device__ __align__(16) __nv_bfloat16 g_ckv_hi[(size_t)NTOK*KVLR];
__device__ __align__(16) __nv_bfloat16 g_ckv_lo[(size_t)NTOK*KVLR];
__device__ __align__(16) __nv_bfloat16 g_kpe_hi[(size_t)NTOK*ROPED];
__device__ __align__(16) __nv_bfloat16 g_kpe_lo[(size_t)NTOK*ROPED];
__device__ __align__(16) __nv_bfloat16 g_kv2_hi[(size_t)NTOK*KV2_N];
__device__ __align__(16) __nv_bfloat16 g_kv2_lo[(size_t)NTOK*KV2_N];
__device__ __align__(16) __nv_bfloat16 g_ao_hi [(size_t)NTOK*VVDIM];
__device__ __align__(16) __nv_bfloat16 g_ao_lo [(size_t)NTOK*VVDIM];
__device__ __align__(16) __nv_bfloat16 g_w1_hi [(size_t)QAKV_V*HIDDIM];
__device__ __align__(16) __nv_bfloat16 g_w1_lo [(size_t)QAKV_V*HIDDIM];
__device__ __align__(16) __nv_bfloat16 g_wqb_hi[(size_t)QDIM*QLR];
__device__ __align__(16) __nv_bfloat16 g_wqb_lo[(size_t)QDIM*QLR];
__device__ __align__(16) __nv_bfloat16 g_w2_hi [(size_t)KV2_N*KVLR];
__device__ __align__(16) __nv_bfloat16 g_w2_lo [(size_t)KV2_N*KVLR];
__device__ __align__(16) __nv_bfloat16 g_wo_hi [(size_t)HIDDIM*VVDIM];
__device__ __align__(16) __nv_bfloat16 g_wo_lo [(size_t)HIDDIM*VVDIM];

// ---------------- helpers ----------------
__device__ __forceinline__ uint32_t smem_u32(const void* p) {
    uint32_t a;
    asm("{ .reg .u64 t; cvta.to.shared.u64 t, %1; cvt.u32.u64 %0, t; }" : "=r"(a) : "l"(p));
    return a;
}
#define CP16(dst, src) \
    asm volatile("cp.async.cg.shared.global [%0], [%1], 16;" :: "r"(dst), "l"(src))
#define CP8(dst, src) \
    asm volatile("cp.async.ca.shared.global [%0], [%1], 8;" :: "r"(dst), "l"(src))
#define CP_COMMIT() asm volatile("cp.async.commit_group;" ::: "memory")
#define CP_WAIT(n)  asm volatile("cp.async.wait_group %0;" :: "n"(n) : "memory")

__device__ __forceinline__ float block_sum256(float v) {
    __shared__ float red[8];
    int lane = threadIdx.x & 31, w = threadIdx.x >> 5;
    #pragma unroll
    for (int o = 16; o; o >>= 1) v += __shfl_xor_sync(0xffffffffu, v, o);
    if (lane == 0) red[w] = v;
    __syncthreads();
    if (threadIdx.x == 0) {
        float t = 0.f;
        #pragma unroll
        for (int i = 0; i < 8; i++) t += red[i];
        red[0] = t;
    }
    __syncthreads();
    float r = red[0];
    __syncthreads();
    return r;
}
__device__ __forceinline__ void split4(const float4 v, __nv_bfloat16* h, __nv_bfloat16* l) {
    float vv[4] = {v.x, v.y, v.z, v.w};
    #pragma unroll
    for (int e = 0; e < 4; e++) {
        h[e] = __float2bfloat16(vv[e]);
        l[e] = __float2bfloat16(vv[e] - __bfloat162float(h[e]));
    }
}

// ================= WMMA split-bf16 GEMM body (single-stage smem, occ 2) =================
#define GBM 128
#define GBN 128
#define GBK 64
#define SPAD 80
#define TILE_E (128*SPAD)
#define STAGE_E (4*TILE_E)
#define GEMM_SMEM (STAGE_E*2)         // 81920 bytes -> 2 CTAs/SM

__device__ __forceinline__ void gemm_body(
    const __nv_bfloat16* __restrict__ Ahi, const __nv_bfloat16* __restrict__ Alo,
    const __nv_bfloat16* __restrict__ Bhi, const __nv_bfloat16* __restrict__ Blo,
    float* __restrict__ C, __nv_bfloat16* __restrict__ Chi, __nv_bfloat16* __restrict__ Clo,
    int Nalloc, int Nvalid, int K, int bmIdx, int bnIdx)
{
    extern __shared__ __align__(32) char gsm[];
    __nv_bfloat16* smb = (__nv_bfloat16*)gsm;
    const uint32_t sb = smem_u32(smb);

    const int tid = threadIdx.x, wid = tid >> 5;
    const int warp_m = wid >> 2;
    const int warp_n = wid & 3;
    const int bm = bmIdx * GBM, bn = bnIdx * GBN;
    const int nch = K / GBK;

    const int sr = tid >> 3;
    const int sc = tid & 7;

    auto load_stage = [&](int c) {
        const int k0 = c * GBK;
        #pragma unroll
        for (int it = 0; it < 4; it++) {
            int r = sr + it * 32;
            uint32_t d = sb + (uint32_t)(r * SPAD + sc * 8) * 2;
            size_t srcA = (size_t)(bm + r) * K + k0 + sc * 8;
            CP16(d + 0 * TILE_E * 2, Ahi + srcA);
            CP16(d + 1 * TILE_E * 2, Alo + srcA);
            int gn = bn + r; if (gn >= Nvalid) gn = Nvalid - 1;
            size_t srcB = (size_t)gn * K + k0 + sc * 8;
            CP16(d + 2 * TILE_E * 2, Bhi + srcB);
            CP16(d + 3 * TILE_E * 2, Blo + srcB);
        }
        CP_COMMIT();
    };

    wmma::fragment<wmma::accumulator, 16, 16, 16, float> facc[4][2];
    #pragma unroll
    for (int mi = 0; mi < 4; mi++)
        #pragma unroll
        for (int ni = 0; ni < 2; ni++) wmma::fill_fragment(facc[mi][ni], 0.0f);

    __nv_bfloat16* sAhi = smb;
    __nv_bfloat16* sAlo = sAhi + TILE_E;
    __nv_bfloat16* sBhi = sAhi + 2 * TILE_E;
    __nv_bfloat16* sBlo = sAhi + 3 * TILE_E;

    load_stage(0);

    for (int c = 0; c < nch; c++) {
        CP_WAIT(0);
        __syncthreads();   // stage c visible

        #pragma unroll
        for (int kk = 0; kk < GBK; kk += 16) {
            wmma::fragment<wmma::matrix_a, 16, 16, 16, __nv_bfloat16, wmma::row_major> fah[4], fal[4];
            #pragma unroll
            for (int mi = 0; mi < 4; mi++) {
                int row = warp_m * 64 + mi * 16;
                wmma::load_matrix_sync(fah[mi], sAhi + row * SPAD + kk, SPAD);
                wmma::load_matrix_sync(fal[mi], sAlo + row * SPAD + kk, SPAD);
            }
            #pragma unroll
            for (int ni = 0; ni < 2; ni++) {
                int col = warp_n * 32 + ni * 16;
                wmma::fragment<wmma::matrix_b, 16, 16, 16, __nv_bfloat16, wmma::col_major> fbh, fbl;
                wmma::load_matrix_sync(fbh, sBhi + col * SPAD + kk, SPAD);
                wmma::load_matrix_sync(fbl, sBlo + col * SPAD + kk, SPAD);
                #pragma unroll
                for (int mi = 0; mi < 4; mi++) {
                    wmma::mma_sync(facc[mi][ni], fah[mi], fbh, facc[mi][ni]);
                    wmma::mma_sync(facc[mi][ni], fah[mi], fbl, facc[mi][ni]);
                    wmma::mma_sync(facc[mi][ni], fal[mi], fbh, facc[mi][ni]);
                }
            }
        }
        __syncthreads();   // all reads done before next load overwrites
        if (c + 1 < nch) load_stage(c + 1);
    }

    if (Chi == nullptr) {
        #pragma unroll
        for (int mi = 0; mi < 4; mi++) {
            int row = bm + warp_m * 64 + mi * 16;
            #pragma unroll
            for (int ni = 0; ni < 2; ni++) {
                int col = bn + warp_n * 32 + ni * 16;
                wmma::store_matrix_sync(C + (size_t)row * Nalloc + col, facc[mi][ni],
                                        Nalloc, wmma::mem_row_major);
            }
        }
    } else {
        float* stg = (float*)gsm + (size_t)wid * (32 * 36);   // 32 rows per warp slab x2 passes
        const int ln = tid & 31;
        #pragma unroll
        for (int half = 0; half < 2; half++) {
            #pragma unroll
            for (int mi = 0; mi < 2; mi++)
                #pragma unroll
                for (int ni = 0; ni < 2; ni++)
                    wmma::store_matrix_sync(stg + (mi * 16) * 36 + ni * 16,
                                            facc[half * 2 + mi][ni], 36, wmma::mem_row_major);
            __syncwarp();
            #pragma unroll
            for (int e = 0; e < 4; e++) {
                int r = e * 8 + (ln >> 2);
                int cc = (ln & 3) * 8;
                __align__(16) __nv_bfloat16 h[8], l[8];
                #pragma unroll
                for (int j = 0; j < 8; j++) {
                    float v = stg[r * 36 + cc + j];
                    h[j] = __float2bfloat16(v);
                    l[j] = __float2bfloat16(v - __bfloat162float(h[j]));
                }
                size_t off = (size_t)(bm + warp_m * 64 + half * 32 + r) * Nalloc
                           + bn + warp_n * 32 + cc;
                *(uint4*)(Chi + off) = *(uint4*)h;
                *(uint4*)(Clo + off) = *(uint4*)l;
            }
            __syncwarp();
        }
    }
}

__global__ __launch_bounds__(256, 2) void gemm_wmma(
    const __nv_bfloat16* __restrict__ Ahi, const __nv_bfloat16* __restrict__ Alo,
    const __nv_bfloat16* __restrict__ Bhi, const __nv_bfloat16* __restrict__ Blo,
    float* __restrict__ C, int Nalloc, int Nvalid, int K)
{
    gemm_body(Ahi, Alo, Bhi, Blo, C, nullptr, nullptr, Nalloc, Nvalid, K,
              blockIdx.y, blockIdx.x);
}

#define DG_T1 ((QDIM/GBN)*(NTOK/GBM))   // 768
#define DG_C1 (QDIM/GBN)                // 24
#define DG_T2 ((KV2_N/GBN)*(NTOK/GBM))  // 1024
#define DG_C2 (KV2_N/GBN)               // 32

__global__ __launch_bounds__(256, 2) void gemm_dual(
    const __nv_bfloat16* __restrict__ A1h, const __nv_bfloat16* __restrict__ A1l,
    const __nv_bfloat16* __restrict__ B1h, const __nv_bfloat16* __restrict__ B1l,
    float* __restrict__ C1,
    const __nv_bfloat16* __restrict__ A2h, const __nv_bfloat16* __restrict__ A2l,
    const __nv_bfloat16* __restrict__ B2h, const __nv_bfloat16* __restrict__ B2l,
    __nv_bfloat16* __restrict__ C2h, __nv_bfloat16* __restrict__ C2l)
{
    int t = blockIdx.x;
    if (t < DG_T1) {
        gemm_body(A1h, A1l, B1h, B1l, C1, nullptr, nullptr,
                  QDIM, QDIM, QLR, t / DG_C1, t % DG_C1);
    } else {
        t -= DG_T1;
        gemm_body(A2h, A2l, B2h, B2l, nullptr, C2h, C2l,
                  KV2_N, KV2_N, KVLR, t / DG_C2, t % DG_C2);
    }
}

// ================= merged split kernel =================
struct SplitSegs {
    const float* s[7];
    __nv_bfloat16 *h[7], *l[7];
};
#define SEG0 ((size_t)NTOK*HIDDIM)
#define SEG1 ((size_t)QLR*HIDDIM)
#define SEG2 ((size_t)KVDIM*HIDDIM)
#define SEG3 ((size_t)QDIM*QLR)
#define SEG4 ((size_t)KNOPE_DIM*KVLR)
#define SEG5 ((size_t)VVDIM*KVLR)
#define SEG6 ((size_t)HIDDIM*VVDIM)
#define SEG_TOTAL (SEG0+SEG1+SEG2+SEG3+SEG4+SEG5+SEG6)
#define SEG_VECS  (SEG_TOTAL/8)

__global__ void split_all_k(SplitSegs segs)
{
    size_t v = (size_t)blockIdx.x * blockDim.x + threadIdx.x;
    if (v >= SEG_VECS) return;
    size_t i = v * 8;
    const size_t sz[7] = {SEG0, SEG1, SEG2, SEG3, SEG4, SEG5, SEG6};
    int seg = 0;
    #pragma unroll
    for (int k = 0; k < 6; k++) {
        if (i >= sz[seg]) { i -= sz[seg]; seg++; }
    }
    const float* s = segs.s[seg];
    __nv_bfloat16* hi = segs.h[seg];
    __nv_bfloat16* lo = segs.l[seg];
    __align__(16) __nv_bfloat16 h[8], l[8];
    split4(*(const float4*)(s + i),     h,     l);
    split4(*(const float4*)(s + i + 4), h + 4, l + 4);
    *(uint4*)(hi + i) = *(uint4*)h;
    *(uint4*)(lo + i) = *(uint4*)l;
}

// ================= merged norms =================
__global__ void norms_k(const float* __restrict__ wq,
                        const float* __restrict__ wkv,
                        const float* __restrict__ sin_t,
                        const float* __restrict__ cos_t)
{
    int row = blockIdx.x;
    const float* base = g_qakv + (size_t)row * QAKV_N;

    {
        float ss = 0.f;
        for (int i = threadIdx.x; i < QLR; i += blockDim.x) { float v = base[i]; ss += v * v; }
        ss = block_sum256(ss);
        float sc = rsqrtf(ss / (float)QLR + 1e-6f);
        for (int i = threadIdx.x; i < QLR; i += blockDim.x) {
            float v = base[i] * sc * wq[i];
            __nv_bfloat16 hh = __float2bfloat16(v);
            g_qn_hi[(size_t)row * QLR + i] = hh;
            g_qn_lo[(size_t)row * QLR + i] = __float2bfloat16(v - __bfloat162float(hh));
        }
    }
    {
        const float* h = base + QLR;
        float ss = 0.f;
        for (int i = threadIdx.x; i < KVLR; i += blockDim.x) { float v = h[i]; ss += v * v; }
        ss = block_sum256(ss);
        float sc = rsqrtf(ss / (float)KVLR + 1e-6f);
        for (int i = threadIdx.x; i < KVLR; i += blockDim.x) {
            float v = h[i] * sc * wkv[i];
            __nv_bfloat16 hh = __float2bfloat16(v);
            g_ckv_hi[(size_t)row * KVLR + i] = hh;
            g_ckv_lo[(size_t)row * KVLR + i] = __float2bfloat16(v - __bfloat162float(hh));
        }
        if (threadIdx.x < ROPED / 2) {
            int i = threadIdx.x;
            int pos = row & (SEQ - 1);
            float s = sin_t[pos * 32 + i], c = cos_t[pos * 32 + i];
            float e = h[KVLR + 2 * i], o = h[KVLR + 2 * i + 1];
            float r0 = e * c - o * s;
            float r1 = e * s + o * c;
            __nv_bfloat16 h0 = __float2bfloat16(r0);
            __nv_bfloat16 h1 = __float2bfloat16(r1);
            size_t off = (size_t)row * ROPED + 2 * i;
            g_kpe_hi[off]     = h0;
            g_kpe_hi[off + 1] = h1;
            g_kpe_lo[off]     = __float2bfloat16(r0 - __bfloat162float(h0));
            g_kpe_lo[off + 1] = __float2bfloat16(r1 - __bfloat162float(h1));
        }
    }
}

// ================= flash attention (R14 verbatim) =================
#define AT_THREADS 256
#define AQS   208
#define AVS   128
#define APSTR 72
#define APS2  80
#define OF_QH 0
#define OF_QL (OF_QH + 64*AQS*2)
#define OF_KH (OF_QL + 64*AQS*2)
#define OF_KL (OF_KH + 64*AQS*2)
#define OF_VH (OF_KL + 64*AQS*2)
#define OF_VL (OF_VH + 64*AVS*2)
#define OF_PS (OF_VL + 64*AVS*2)
#define OF_PH (OF_PS + 64*APSTR*4)
#define OF_PL (OF_PH + 64*APS2*2)
#define OF_PV (OF_PL + 64*APS2*2)
#define OF_RW (OF_PV + 64*VDIM*4)
#define ATT_SMEM (OF_RW + 3*64*4)     // 211712

__global__ __launch_bounds__(AT_THREADS) void attn_k(
    const float* __restrict__ sin_t, const float* __restrict__ cos_t)
{
    extern __shared__ __align__(32) char asmm[];
    const uint32_t sbA = smem_u32(asmm);
    __nv_bfloat16* sQh = (__nv_bfloat16*)(asmm + OF_QH);
    __nv_bfloat16* sQl = (__nv_bfloat16*)(asmm + OF_QL);
    __nv_bfloat16* sKh = (__nv_bfloat16*)(asmm + OF_KH);
    __nv_bfloat16* sKl = (__nv_bfloat16*)(asmm + OF_KL);
    __nv_bfloat16* sVh = (__nv_bfloat16*)(asmm + OF_VH);
    __nv_bfloat16* sVl = (__nv_bfloat16*)(asmm + OF_VL);
    float* sPs = (float*)(asmm + OF_PS);
    __nv_bfloat16* sPh = (__nv_bfloat16*)(asmm + OF_PH);
    __nv_bfloat16* sPl = (__nv_bfloat16*)(asmm + OF_PL);
    float* sPV  = (float*)(asmm + OF_PV);
    float* mrow = (float*)(asmm + OF_RW);
    float* lrow = mrow + 64;
    float* arow = lrow + 64;

    const int qt = (int)gridDim.x - 1 - (int)blockIdx.x;
    const int hh = blockIdx.y, b = blockIdx.z;
    const int tid = threadIdx.x, lane = tid & 31, wid = tid >> 5;
    const int warp_m = wid >> 2;
    const int warp_n = wid & 3;
    const int q0 = qt * 64;
    const int grow0 = b * SEQ + q0;
    const int pr = tid >> 2;
    const int cb = (tid & 3) * 4;

    const float scale = 0.07216878364870323f;

    auto prefetch_K = [&](int kt) {
        const int gk0 = b * SEQ + kt * 64;
        for (int t = tid; t < 64 * 48; t += AT_THREADS) {
            int r = t / 48, c = t % 48;
            size_t src;
            const __nv_bfloat16 *ph, *pl;
            if (c < 32) {
                src = (size_t)(gk0 + r) * KV2_N + hh * NOPE + c * 4;
                ph = g_kv2_hi; pl = g_kv2_lo;
            } else {
                src = (size_t)(gk0 + r) * ROPED + (c - 32) * 4;
                ph = g_kpe_hi; pl = g_kpe_lo;
            }
            uint32_t d = (uint32_t)(r * AQS + c * 4) * 2;
            CP8(sbA + OF_KH + d, ph + src);
            CP8(sbA + OF_KL + d, pl + src);
        }
    };
    auto prefetch_V = [&](int kt) {
        const int gk0 = b * SEQ + kt * 64;
        for (int t = tid; t < 64 * 16; t += AT_THREADS) {
            int r = t / 16, c = t % 16;
            size_t src = (size_t)(gk0 + r) * KV2_N + KNOPE_DIM + hh * VDIM + c * 8;
            uint32_t d = (uint32_t)(r * AVS + c * 8) * 2;
            CP16(sbA + OF_VH + d, g_kv2_hi + src);
            CP16(sbA + OF_VL + d, g_kv2_lo + src);
        }
    };

    for (int t = tid; t < 64 * 48; t += AT_THREADS) {
        int r = t / 48, c = t % 48;
        float4 v = *(const float4*)(g_q + (size_t)(grow0 + r) * QDIM + hh * HD + c * 4);
        if (c >= 32) {
            int pos = q0 + r;
            int i0 = (c * 4 - NOPE) >> 1;
            float s0 = sin_t[pos * 32 + i0],     c0 = cos_t[pos * 32 + i0];
            float s1 = sin_t[pos * 32 + i0 + 1], c1 = cos_t[pos * 32 + i0 + 1];
            float e0 = v.x, o0 = v.y, e1 = v.z, o1 = v.w;
            v.x = e0 * c0 - o0 * s0;  v.y = e0 * s0 + o0 * c0;
            v.z = e1 * c1 - o1 * s1;  v.w = e1 * s1 + o1 * c1;
        }
        v.x *= scale; v.y *= scale; v.z *= scale; v.w *= scale;
        __align__(8) __nv_bfloat16 h[4], l[4];
        split4(v, h, l);
        *(uint2*)(sQh + r * AQS + c * 4) = *(uint2*)h;
        *(uint2*)(sQl + r * AQS + c * 4) = *(uint2*)l;
    }
    if (tid < 64) { mrow[tid] = -INFINITY; lrow[tid] = 0.f; }

    prefetch_K(0);
    prefetch_V(0);
    CP_COMMIT();

    float4 O4[8];
    #pragma unroll
    for (int k = 0; k < 8; k++) O4[k] = make_float4(0.f, 0.f, 0.f, 0.f);

    __syncthreads();

    for (int kt = 0; kt <= qt; kt++) {
        const int k0 = kt * 64;

        CP_WAIT(0);
        __syncthreads();

        {
            wmma::fragment<wmma::accumulator, 16, 16, 16, float> fs[2];
            #pragma unroll
            for (int mi = 0; mi < 2; mi++) wmma::fill_fragment(fs[mi], 0.0f);
            #pragma unroll
            for (int kk = 0; kk < HD; kk += 16) {
                wmma::fragment<wmma::matrix_a, 16, 16, 16, __nv_bfloat16, wmma::row_major> qh[2], ql[2];
                #pragma unroll
                for (int mi = 0; mi < 2; mi++) {
                    int row = warp_m * 32 + mi * 16;
                    wmma::load_matrix_sync(qh[mi], sQh + row * AQS + kk, AQS);
                    wmma::load_matrix_sync(ql[mi], sQl + row * AQS + kk, AQS);
                }
                wmma::fragment<wmma::matrix_b, 16, 16, 16, __nv_bfloat16, wmma::col_major> kh, kl;
                int col = warp_n * 16;
                wmma::load_matrix_sync(kh, sKh + col * AQS + kk, AQS);
                wmma::load_matrix_sync(kl, sKl + col * AQS + kk, AQS);
                #pragma unroll
                for (int mi = 0; mi < 2; mi++) {
                    wmma::mma_sync(fs[mi], qh[mi], kh, fs[mi]);
                    wmma::mma_sync(fs[mi], qh[mi], kl, fs[mi]);
                    wmma::mma_sync(fs[mi], ql[mi], kh, fs[mi]);
                }
            }
            #pragma unroll
            for (int mi = 0; mi < 2; mi++) {
                int row = warp_m * 32 + mi * 16;
                wmma::store_matrix_sync(sPs + row * APSTR + warp_n * 16, fs[mi],
                                        APSTR, wmma::mem_row_major);
            }
        }
        __syncthreads();

        if (kt < qt) { prefetch_K(kt + 1); CP_COMMIT(); }

        {
            int rbase = wid * 8;
            #pragma unroll
            for (int rr = 0; rr < 8; rr++) {
                int r = rbase + rr;
                int qi = q0 + r;
                float v0 = (k0 + lane      <= qi) ? sPs[r * APSTR + lane]      : -1e30f;
                float v1 = (k0 + 32 + lane <= qi) ? sPs[r * APSTR + 32 + lane] : -1e30f;
                float mx = fmaxf(v0, v1);
                #pragma unroll
                for (int o = 16; o; o >>= 1) mx = fmaxf(mx, __shfl_xor_sync(0xffffffffu, mx, o));
                float mold = mrow[r];
                float mnew = fmaxf(mold, mx);
                float p0 = __expf(v0 - mnew), p1 = __expf(v1 - mnew);
                __nv_bfloat16 h0 = __float2bfloat16(p0);
                __nv_bfloat16 h1 = __float2bfloat16(p1);
                sPh[r * APS2 + lane]      = h0;
                sPh[r * APS2 + 32 + lane] = h1;
                sPl[r * APS2 + lane]      = __float2bfloat16(p0 - __bfloat162float(h0));
                sPl[r * APS2 + 32 + lane] = __float2bfloat16(p1 - __bfloat162float(h1));
                float s = p0 + p1;
                #pragma unroll
                for (int o = 16; o; o >>= 1) s += __shfl_xor_sync(0xffffffffu, s, o);
                if (lane == 0) {
                    float a = (mold > -1e30f) ? __expf(mold - mnew) : 0.f;
                    arow[r] = a;
                    lrow[r] = lrow[r] * a + s;
                    mrow[r] = mnew;
                }
            }
        }
        __syncthreads();

        {
            wmma::fragment<wmma::accumulator, 16, 16, 16, float> fo[2][2];
            #pragma unroll
            for (int mi = 0; mi < 2; mi++)
                #pragma unroll
                for (int ni = 0; ni < 2; ni++) wmma::fill_fragment(fo[mi][ni], 0.0f);
            #pragma unroll
            for (int kk = 0; kk < 64; kk += 16) {
                wmma::fragment<wmma::matrix_a, 16, 16, 16, __nv_bfloat16, wmma::row_major> ph[2], pl[2];
                #pragma unroll
                for (int mi = 0; mi < 2; mi++) {
                    int row = warp_m * 32 + mi * 16;
                    wmma::load_matrix_sync(ph[mi], sPh + row * APS2 + kk, APS2);
                    wmma::load_matrix_sync(pl[mi], sPl + row * APS2 + kk, APS2);
                }
                #pragma unroll
                for (int ni = 0; ni < 2; ni++) {
                    int col = warp_n * 32 + ni * 16;
                    wmma::fragment<wmma::matrix_b, 16, 16, 16, __nv_bfloat16, wmma::row_major> vh, vl;
                    wmma::load_matrix_sync(vh, sVh + kk * AVS + col, AVS);
                    wmma::load_matrix_sync(vl, sVl + kk * AVS + col, AVS);
                    #pragma unroll
                    for (int mi = 0; mi < 2; mi++) {
                        wmma::mma_sync(fo[mi][ni], ph[mi], vh, fo[mi][ni]);
                        wmma::mma_sync(fo[mi][ni], ph[mi], vl, fo[mi][ni]);
                        wmma::mma_sync(fo[mi][ni], pl[mi], vh, fo[mi][ni]);
                    }
                }
            }
            #pragma unroll
            for (int mi = 0; mi < 2; mi++) {
                int row = warp_m * 32 + mi * 16;
                #pragma unroll
                for (int ni = 0; ni < 2; ni++) {
                    int col = warp_n * 32 + ni * 16;
                    wmma::store_matrix_sync(sPV + row * VDIM + col, fo[mi][ni],
                                            VDIM, wmma::mem_row_major);
                }
            }
        }
        __syncthreads();

        if (kt < qt) { prefetch_V(kt + 1); CP_COMMIT(); }

        {
            float a = arow[pr];
            #pragma unroll
            for (int k = 0; k < 8; k++) {
                float4 pv = *(float4*)(sPV + pr * VDIM + cb + 16 * k);
                O4[k].x = O4[k].x * a + pv.x;
                O4[k].y = O4[k].y * a + pv.y;
                O4[k].z = O4[k].z * a + pv.z;
                O4[k].w = O4[k].w * a + pv.w;
            }
        }
    }

    float inv = 1.f / lrow[pr];
    #pragma unroll
    for (int k = 0; k < 8; k++) {
        float4 v = make_float4(O4[k].x * inv, O4[k].y * inv, O4[k].z * inv, O4[k].w * inv);
        __align__(8) __nv_bfloat16 h[4], l[4];
        split4(v, h, l);
        size_t off = (size_t)(grow0 + pr) * VVDIM + hh * VDIM + cb + 16 * k;
        *(uint2*)(g_ao_hi + off) = *(uint2*)h;
        *(uint2*)(g_ao_lo + off) = *(uint2*)l;
    }
}

// ================= host launch =================
extern "C" void kernel_launch(void* const* d_in, const int* in_sizes, int n_in,
                              void* d_out, int out_size)
{
    const float* x        = (const float*)d_in[0];
    const float* wq_a     = (const float*)d_in[1];
    const float* w_qa_ln  = (const float*)d_in[2];
    const float* wq_b     = (const float*)d_in[3];
    const float* wkv_a    = (const float*)d_in[4];
    const float* w_kva_ln = (const float*)d_in[5];
    const float* wk_b     = (const float*)d_in[6];
    const float* wv_b     = (const float*)d_in[7];
    const float* wo       = (const float*)d_in[8];
    const float* rsin     = (const float*)d_in[9];
    const float* rcos     = (const float*)d_in[10];
    float* out = (float*)d_out;

    float *qakv, *q;
    cudaGetSymbolAddress((void**)&qakv, g_qakv);
    cudaGetSymbolAddress((void**)&q,    g_q);

    __nv_bfloat16 *xh, *xl, *qnh, *qnl, *ckvh, *ckvl, *aoh, *aol, *kv2h, *kv2l;
    __nv_bfloat16 *w1h, *w1l, *wqbh, *wqbl, *w2h, *w2l, *woh, *wol;
    cudaGetSymbolAddress((void**)&xh,   g_x_hi);   cudaGetSymbolAddress((void**)&xl,   g_x_lo);
    cudaGetSymbolAddress((void**)&qnh,  g_qn_hi);  cudaGetSymbolAddress((void**)&qnl,  g_qn_lo);
    cudaGetSymbolAddress((void**)&ckvh, g_ckv_hi); cudaGetSymbolAddress((void**)&ckvl, g_ckv_lo);
    cudaGetSymbolAddress((void**)&aoh,  g_ao_hi);  cudaGetSymbolAddress((void**)&aol,  g_ao_lo);
    cudaGetSymbolAddress((void**)&kv2h, g_kv2_hi); cudaGetSymbolAddress((void**)&kv2l, g_kv2_lo);
    cudaGetSymbolAddress((void**)&w1h,  g_w1_hi);  cudaGetSymbolAddress((void**)&w1l,  g_w1_lo);
    cudaGetSymbolAddress((void**)&wqbh, g_wqb_hi); cudaGetSymbolAddress((void**)&wqbl, g_wqb_lo);
    cudaGetSymbolAddress((void**)&w2h,  g_w2_hi);  cudaGetSymbolAddress((void**)&w2l,  g_w2_lo);
    cudaGetSymbolAddress((void**)&woh,  g_wo_hi);  cudaGetSymbolAddress((void**)&wol,  g_wo_lo);

    cudaFuncSetAttribute(gemm_wmma, cudaFuncAttributeMaxDynamicSharedMemorySize, GEMM_SMEM);
    cudaFuncSetAttribute(gemm_dual, cudaFuncAttributeMaxDynamicSharedMemorySize, GEMM_SMEM);
    cudaFuncSetAttribute(attn_k,    cudaFuncAttributeMaxDynamicSharedMemorySize, ATT_SMEM);

    SplitSegs segs;
    segs.s[0] = x;     segs.h[0] = xh;   segs.l[0] = xl;
    segs.s[1] = wq_a;  segs.h[1] = w1h;  segs.l[1] = w1l;
    segs.s[2] = wkv_a; segs.h[2] = w1h + (size_t)QLR * HIDDIM;
                       segs.l[2] = w1l + (size_t)QLR * HIDDIM;
    segs.s[3] = wq_b;  segs.h[3] = wqbh; segs.l[3] = wqbl;
    segs.s[4] = wk_b;  segs.h[4] = w2h;  segs.l[4] = w2l;
    segs.s[5] = wv_b;  segs.h[5] = w2h + (size_t)KNOPE_DIM * KVLR;
                       segs.l[5] = w2l + (size_t)KNOPE_DIM * KVLR;
    segs.s[6] = wo;    segs.h[6] = woh;  segs.l[6] = wol;
    split_all_k<<<(unsigned)((SEG_VECS + 255) / 256), 256>>>(segs);

    gemm_wmma<<<dim3(QAKV_N / GBN, NTOK / GBM), 256, GEMM_SMEM>>>(
        xh, xl, w1h, w1l, qakv, QAKV_N, QAKV_V, HIDDIM);

    norms_k<<<NTOK, 256>>>(w_qa_ln, w_kva_ln, rsin, rcos);

    gemm_dual<<<DG_T1 + DG_T2, 256, GEMM_SMEM>>>(
        qnh, qnl, wqbh, wqbl, q,
        ckvh, ckvl, w2h, w2l, kv2h, kv2l);

    attn_k<<<dim3(SEQ / 64, HEADS, BATCH), AT_THREADS, ATT_SMEM>>>(rsin, rcos);

    gemm_wmma<<<dim3(HIDDIM / GBN, NTOK / GBM), 256, GEMM_SMEM>>>(
        aoh, aol, woh, wol, out, HIDDIM, HIDDIM, VVDIM);
}

// round 17
// speedup vs baseline: 1.5758x; 1.5758x over previous
#include <cuda_runtime.h>
#include <cuda_bf16.h>
#include <mma.h>
#include <math.h>
#include <stdint.h>

using namespace nvcuda;

// ---------------- problem constants ----------------
#define NTOK   4096            // B*S
#define HIDDIM 2048
#define QLR    1536
#define KVLR   512
#define HEADS  16
#define NOPE   128
#define ROPED  64
#define HD     192             // NOPE+ROPE
#define VDIM   128
#define SEQ    1024
#define BATCH  4
#define QDIM   (HEADS*HD)      // 3072
#define KVDIM  (KVLR+ROPED)    // 576
#define QAKV_N 2176            // QLR + KVDIM padded to x128
#define QAKV_V 2112
#define KNOPE_DIM (HEADS*NOPE) // 2048
#define VVDIM  (HEADS*VDIM)    // 2048
#define KV2_N  4096            // knope | v

// ---------------- fp32 scratch ----------------
__device__ float g_qakv [(size_t)NTOK*QAKV_N];
__device__ float g_q    [(size_t)NTOK*QDIM];

// ---------------- bf16 hi/lo scratch ----------------
__device__ __align__(16) __nv_bfloat16 g_x_hi  [(size_t)NTOK*HIDDIM];
__device__ __align__(16) __nv_bfloat16 g_x_lo  [(size_t)NTOK*HIDDIM];
__device__ __align__(16) __nv_bfloat16 g_qn_hi [(size_t)NTOK*QLR];
__device__ __align__(16) __nv_bfloat16 g_qn_lo [(size_t)NTOK*QLR];
__device__ __align__(16) __nv_bfloat16 g_ckv_hi[(size_t)NTOK*KVLR];
__device__ __align__(16) __nv_bfloat16 g_ckv_lo[(size_t)NTOK*KVLR];
__device__ __align__(16) __nv_bfloat16 g_kpe_hi[(size_t)NTOK*ROPED];
__device__ __align__(16) __nv_bfloat16 g_kpe_lo[(size_t)NTOK*ROPED];
__device__ __align__(16) __nv_bfloat16 g_kv2_hi[(size_t)NTOK*KV2_N];
__device__ __align__(16) __nv_bfloat16 g_kv2_lo[(size_t)NTOK*KV2_N];
__device__ __align__(16) __nv_bfloat16 g_ao_hi [(size_t)NTOK*VVDIM];
__device__ __align__(16) __nv_bfloat16 g_ao_lo [(size_t)NTOK*VVDIM];
__device__ __align__(16) __nv_bfloat16 g_w1_hi [(size_t)QAKV_V*HIDDIM];
__device__ __align__(16) __nv_bfloat16 g_w1_lo [(size_t)QAKV_V*HIDDIM];
__device__ __align__(16) __nv_bfloat16 g_wqb_hi[(size_t)QDIM*QLR];
__device__ __align__(16) __nv_bfloat16 g_wqb_lo[(size_t)QDIM*QLR];
__device__ __align__(16) __nv_bfloat16 g_w2_hi [(size_t)KV2_N*KVLR];
__device__ __align__(16) __nv_bfloat16 g_w2_lo [(size_t)KV2_N*KVLR];
__device__ __align__(16) __nv_bfloat16 g_wo_hi [(size_t)HIDDIM*VVDIM];
__device__ __align__(16) __nv_bfloat16 g_wo_lo [(size_t)HIDDIM*VVDIM];

// ---------------- helpers ----------------
__device__ __forceinline__ uint32_t smem_u32(const void* p) {
    uint32_t a;
    asm("{ .reg .u64 t; cvta.to.shared.u64 t, %1; cvt.u32.u64 %0, t; }" : "=r"(a) : "l"(p));
    return a;
}
#define CP16(dst, src) \
    asm volatile("cp.async.cg.shared.global [%0], [%1], 16;" :: "r"(dst), "l"(src))
#define CP_COMMIT() asm volatile("cp.async.commit_group;" ::: "memory")
#define CP_WAIT(n)  asm volatile("cp.async.wait_group %0;" :: "n"(n) : "memory")

__device__ __forceinline__ float block_sum256(float v) {
    __shared__ float red[8];
    int lane = threadIdx.x & 31, w = threadIdx.x >> 5;
    #pragma unroll
    for (int o = 16; o; o >>= 1) v += __shfl_xor_sync(0xffffffffu, v, o);
    if (lane == 0) red[w] = v;
    __syncthreads();
    if (threadIdx.x == 0) {
        float t = 0.f;
        #pragma unroll
        for (int i = 0; i < 8; i++) t += red[i];
        red[0] = t;
    }
    __syncthreads();
    float r = red[0];
    __syncthreads();
    return r;
}
__device__ __forceinline__ void split4(const float4 v, __nv_bfloat16* h, __nv_bfloat16* l) {
    float vv[4] = {v.x, v.y, v.z, v.w};
    #pragma unroll
    for (int e = 0; e < 4; e++) {
        h[e] = __float2bfloat16(vv[e]);
        l[e] = __float2bfloat16(vv[e] - __bfloat162float(h[e]));
    }
}

// ================= WMMA split-bf16 GEMM body (R14 config — proven optimum) =================
#define GBM 128
#define GBN 128
#define GBK 64
#define SPAD 80
#define TILE_E (128*SPAD)
#define STAGE_E (4*TILE_E)
#define GEMM_SMEM (2*STAGE_E*2)       // 163840 bytes

__device__ __forceinline__ void gemm_body(
    const __nv_bfloat16* __restrict__ Ahi, const __nv_bfloat16* __restrict__ Alo,
    const __nv_bfloat16* __restrict__ Bhi, const __nv_bfloat16* __restrict__ Blo,
    float* __restrict__ C, __nv_bfloat16* __restrict__ Chi, __nv_bfloat16* __restrict__ Clo,
    int Nalloc, int Nvalid, int K, int bmIdx, int bnIdx)
{
    extern __shared__ __align__(32) char gsm[];
    __nv_bfloat16* smb = (__nv_bfloat16*)gsm;
    const uint32_t sb = smem_u32(smb);

    const int tid = threadIdx.x, wid = tid >> 5;
    const int warp_m = wid >> 2;
    const int warp_n = wid & 3;
    const int bm = bmIdx * GBM, bn = bnIdx * GBN;
    const int nch = K / GBK;

    const int sr = tid >> 3;
    const int sc = tid & 7;

    auto load_stage = [&](int s, int c) {
        const int k0 = c * GBK;
        const uint32_t base = sb + (uint32_t)s * (STAGE_E * 2);
        #pragma unroll
        for (int it = 0; it < 4; it++) {
            int r = sr + it * 32;
            uint32_t d = base + (uint32_t)(r * SPAD + sc * 8) * 2;
            size_t srcA = (size_t)(bm + r) * K + k0 + sc * 8;
            CP16(d + 0 * TILE_E * 2, Ahi + srcA);
            CP16(d + 1 * TILE_E * 2, Alo + srcA);
            int gn = bn + r; if (gn >= Nvalid) gn = Nvalid - 1;
            size_t srcB = (size_t)gn * K + k0 + sc * 8;
            CP16(d + 2 * TILE_E * 2, Bhi + srcB);
            CP16(d + 3 * TILE_E * 2, Blo + srcB);
        }
        CP_COMMIT();
    };

    wmma::fragment<wmma::accumulator, 16, 16, 16, float> facc[4][2];
    #pragma unroll
    for (int mi = 0; mi < 4; mi++)
        #pragma unroll
        for (int ni = 0; ni < 2; ni++) wmma::fill_fragment(facc[mi][ni], 0.0f);

    load_stage(0, 0);

    for (int c = 0; c < nch; c++) {
        if (c + 1 < nch) {
            load_stage((c + 1) & 1, c + 1);
            CP_WAIT(1);
        } else {
            CP_WAIT(0);
        }
        __syncthreads();

        const int s = c & 1;
        __nv_bfloat16* sAhi = smb + s * STAGE_E;
        __nv_bfloat16* sAlo = sAhi + TILE_E;
        __nv_bfloat16* sBhi = sAhi + 2 * TILE_E;
        __nv_bfloat16* sBlo = sAhi + 3 * TILE_E;

        #pragma unroll
        for (int kk = 0; kk < GBK; kk += 16) {
            wmma::fragment<wmma::matrix_a, 16, 16, 16, __nv_bfloat16, wmma::row_major> fah[4], fal[4];
            #pragma unroll
            for (int mi = 0; mi < 4; mi++) {
                int row = warp_m * 64 + mi * 16;
                wmma::load_matrix_sync(fah[mi], sAhi + row * SPAD + kk, SPAD);
                wmma::load_matrix_sync(fal[mi], sAlo + row * SPAD + kk, SPAD);
            }
            #pragma unroll
            for (int ni = 0; ni < 2; ni++) {
                int col = warp_n * 32 + ni * 16;
                wmma::fragment<wmma::matrix_b, 16, 16, 16, __nv_bfloat16, wmma::col_major> fbh, fbl;
                wmma::load_matrix_sync(fbh, sBhi + col * SPAD + kk, SPAD);
                wmma::load_matrix_sync(fbl, sBlo + col * SPAD + kk, SPAD);
                #pragma unroll
                for (int mi = 0; mi < 4; mi++) {
                    wmma::mma_sync(facc[mi][ni], fah[mi], fbh, facc[mi][ni]);
                    wmma::mma_sync(facc[mi][ni], fah[mi], fbl, facc[mi][ni]);
                    wmma::mma_sync(facc[mi][ni], fal[mi], fbh, facc[mi][ni]);
                }
            }
        }
        __syncthreads();
    }

    if (Chi == nullptr) {
        #pragma unroll
        for (int mi = 0; mi < 4; mi++) {
            int row = bm + warp_m * 64 + mi * 16;
            #pragma unroll
            for (int ni = 0; ni < 2; ni++) {
                int col = bn + warp_n * 32 + ni * 16;
                wmma::store_matrix_sync(C + (size_t)row * Nalloc + col, facc[mi][ni],
                                        Nalloc, wmma::mem_row_major);
            }
        }
    } else {
        float* stg = (float*)gsm + (size_t)wid * (64 * 36);
        #pragma unroll
        for (int mi = 0; mi < 4; mi++)
            #pragma unroll
            for (int ni = 0; ni < 2; ni++)
                wmma::store_matrix_sync(stg + (mi * 16) * 36 + ni * 16, facc[mi][ni],
                                        36, wmma::mem_row_major);
        __syncwarp();
        const int ln = tid & 31;
        #pragma unroll
        for (int e = 0; e < 8; e++) {
            int r = e * 8 + (ln >> 2);
            int cc = (ln & 3) * 8;
            __align__(16) __nv_bfloat16 h[8], l[8];
            #pragma unroll
            for (int j = 0; j < 8; j++) {
                float v = stg[r * 36 + cc + j];
                h[j] = __float2bfloat16(v);
                l[j] = __float2bfloat16(v - __bfloat162float(h[j]));
            }
            size_t off = (size_t)(bm + warp_m * 64 + r) * Nalloc + bn + warp_n * 32 + cc;
            *(uint4*)(Chi + off) = *(uint4*)h;
            *(uint4*)(Clo + off) = *(uint4*)l;
        }
    }
}

__global__ __launch_bounds__(256) void gemm_wmma(
    const __nv_bfloat16* __restrict__ Ahi, const __nv_bfloat16* __restrict__ Alo,
    const __nv_bfloat16* __restrict__ Bhi, const __nv_bfloat16* __restrict__ Blo,
    float* __restrict__ C, int Nalloc, int Nvalid, int K)
{
    gemm_body(Ahi, Alo, Bhi, Blo, C, nullptr, nullptr, Nalloc, Nvalid, K,
              blockIdx.y, blockIdx.x);
}

#define DG_T1 ((QDIM/GBN)*(NTOK/GBM))   // 768
#define DG_C1 (QDIM/GBN)                // 24
#define DG_T2 ((KV2_N/GBN)*(NTOK/GBM))  // 1024
#define DG_C2 (KV2_N/GBN)               // 32

__global__ __launch_bounds__(256) void gemm_dual(
    const __nv_bfloat16* __restrict__ A1h, const __nv_bfloat16* __restrict__ A1l,
    const __nv_bfloat16* __restrict__ B1h, const __nv_bfloat16* __restrict__ B1l,
    float* __restrict__ C1,
    const __nv_bfloat16* __restrict__ A2h, const __nv_bfloat16* __restrict__ A2l,
    const __nv_bfloat16* __restrict__ B2h, const __nv_bfloat16* __restrict__ B2l,
    __nv_bfloat16* __restrict__ C2h, __nv_bfloat16* __restrict__ C2l)
{
    int t = blockIdx.x;
    if (t < DG_T1) {
        gemm_body(A1h, A1l, B1h, B1l, C1, nullptr, nullptr,
                  QDIM, QDIM, QLR, t / DG_C1, t % DG_C1);
    } else {
        t -= DG_T1;
        gemm_body(A2h, A2l, B2h, B2l, nullptr, C2h, C2l,
                  KV2_N, KV2_N, KVLR, t / DG_C2, t % DG_C2);
    }
}

// ================= merged split kernel =================
struct SplitSegs {
    const float* s[7];
    __nv_bfloat16 *h[7], *l[7];
};
#define SEG0 ((size_t)NTOK*HIDDIM)
#define SEG1 ((size_t)QLR*HIDDIM)
#define SEG2 ((size_t)KVDIM*HIDDIM)
#define SEG3 ((size_t)QDIM*QLR)
#define SEG4 ((size_t)KNOPE_DIM*KVLR)
#define SEG5 ((size_t)VVDIM*KVLR)
#define SEG6 ((size_t)HIDDIM*VVDIM)
#define SEG_TOTAL (SEG0+SEG1+SEG2+SEG3+SEG4+SEG5+SEG6)
#define SEG_VECS  (SEG_TOTAL/8)

__global__ void split_all_k(SplitSegs segs)
{
    size_t v = (size_t)blockIdx.x * blockDim.x + threadIdx.x;
    if (v >= SEG_VECS) return;
    size_t i = v * 8;
    const size_t sz[7] = {SEG0, SEG1, SEG2, SEG3, SEG4, SEG5, SEG6};
    int seg = 0;
    #pragma unroll
    for (int k = 0; k < 6; k++) {
        if (i >= sz[seg]) { i -= sz[seg]; seg++; }
    }
    const float* s = segs.s[seg];
    __nv_bfloat16* hi = segs.h[seg];
    __nv_bfloat16* lo = segs.l[seg];
    __align__(16) __nv_bfloat16 h[8], l[8];
    split4(*(const float4*)(s + i),     h,     l);
    split4(*(const float4*)(s + i + 4), h + 4, l + 4);
    *(uint4*)(hi + i) = *(uint4*)h;
    *(uint4*)(lo + i) = *(uint4*)l;
}

// ================= merged norms =================
__global__ void norms_k(const float* __restrict__ wq,
                        const float* __restrict__ wkv,
                        const float* __restrict__ sin_t,
                        const float* __restrict__ cos_t)
{
    int row = blockIdx.x;
    const float* base = g_qakv + (size_t)row * QAKV_N;

    {
        float ss = 0.f;
        for (int i = threadIdx.x; i < QLR; i += blockDim.x) { float v = base[i]; ss += v * v; }
        ss = block_sum256(ss);
        float sc = rsqrtf(ss / (float)QLR + 1e-6f);
        for (int i = threadIdx.x; i < QLR; i += blockDim.x) {
            float v = base[i] * sc * wq[i];
            __nv_bfloat16 hh = __float2bfloat16(v);
            g_qn_hi[(size_t)row * QLR + i] = hh;
            g_qn_lo[(size_t)row * QLR + i] = __float2bfloat16(v - __bfloat162float(hh));
        }
    }
    {
        const float* h = base + QLR;
        float ss = 0.f;
        for (int i = threadIdx.x; i < KVLR; i += blockDim.x) { float v = h[i]; ss += v * v; }
        ss = block_sum256(ss);
        float sc = rsqrtf(ss / (float)KVLR + 1e-6f);
        for (int i = threadIdx.x; i < KVLR; i += blockDim.x) {
            float v = h[i] * sc * wkv[i];
            __nv_bfloat16 hh = __float2bfloat16(v);
            g_ckv_hi[(size_t)row * KVLR + i] = hh;
            g_ckv_lo[(size_t)row * KVLR + i] = __float2bfloat16(v - __bfloat162float(hh));
        }
        if (threadIdx.x < ROPED / 2) {
            int i = threadIdx.x;
            int pos = row & (SEQ - 1);
            float s = sin_t[pos * 32 + i], c = cos_t[pos * 32 + i];
            float e = h[KVLR + 2 * i], o = h[KVLR + 2 * i + 1];
            float r0 = e * c - o * s;
            float r1 = e * s + o * c;
            __nv_bfloat16 h0 = __float2bfloat16(r0);
            __nv_bfloat16 h1 = __float2bfloat16(r1);
            size_t off = (size_t)row * ROPED + 2 * i;
            g_kpe_hi[off]     = h0;
            g_kpe_hi[off + 1] = h1;
            g_kpe_lo[off]     = __float2bfloat16(r0 - __bfloat162float(h0));
            g_kpe_lo[off + 1] = __float2bfloat16(r1 - __bfloat162float(h1));
        }
    }
}

// ================= flash attention: WMMA, cp.async K/V prefetch (16B vectorized) =================
#define AT_THREADS 256
#define AQS   208
#define AVS   128
#define APSTR 72
#define APS2  80
#define OF_QH 0
#define OF_QL (OF_QH + 64*AQS*2)
#define OF_KH (OF_QL + 64*AQS*2)
#define OF_KL (OF_KH + 64*AQS*2)
#define OF_VH (OF_KL + 64*AQS*2)
#define OF_VL (OF_VH + 64*AVS*2)
#define OF_PS (OF_VL + 64*AVS*2)
#define OF_PH (OF_PS + 64*APSTR*4)
#define OF_PL (OF_PH + 64*APS2*2)
#define OF_PV (OF_PL + 64*APS2*2)
#define OF_RW (OF_PV + 64*VDIM*4)
#define ATT_SMEM (OF_RW + 3*64*4)     // 211712

__global__ __launch_bounds__(AT_THREADS) void attn_k(
    const float* __restrict__ sin_t, const float* __restrict__ cos_t)
{
    extern __shared__ __align__(32) char asmm[];
    const uint32_t sbA = smem_u32(asmm);
    __nv_bfloat16* sQh = (__nv_bfloat16*)(asmm + OF_QH);
    __nv_bfloat16* sQl = (__nv_bfloat16*)(asmm + OF_QL);
    __nv_bfloat16* sKh = (__nv_bfloat16*)(asmm + OF_KH);
    __nv_bfloat16* sKl = (__nv_bfloat16*)(asmm + OF_KL);
    __nv_bfloat16* sVh = (__nv_bfloat16*)(asmm + OF_VH);
    __nv_bfloat16* sVl = (__nv_bfloat16*)(asmm + OF_VL);
    float* sPs = (float*)(asmm + OF_PS);
    __nv_bfloat16* sPh = (__nv_bfloat16*)(asmm + OF_PH);
    __nv_bfloat16* sPl = (__nv_bfloat16*)(asmm + OF_PL);
    float* sPV  = (float*)(asmm + OF_PV);
    float* mrow = (float*)(asmm + OF_RW);
    float* lrow = mrow + 64;
    float* arow = lrow + 64;

    const int qt = (int)gridDim.x - 1 - (int)blockIdx.x;  // heaviest-first
    const int hh = blockIdx.y, b = blockIdx.z;
    const int tid = threadIdx.x, lane = tid & 31, wid = tid >> 5;
    const int warp_m = wid >> 2;
    const int warp_n = wid & 3;
    const int q0 = qt * 64;
    const int grow0 = b * SEQ + q0;
    const int pr = tid >> 2;
    const int cb = (tid & 3) * 4;

    const float scale = 0.07216878364870323f;   // 1/sqrt(192)

    // K prefetch: 16B vectors, 24 chunks per row (16 from kv2-nope, 8 from kpe)
    auto prefetch_K = [&](int kt) {
        const int gk0 = b * SEQ + kt * 64;
        for (int t = tid; t < 64 * 24; t += AT_THREADS) {
            int r = t / 24, c = t % 24;
            size_t src;
            const __nv_bfloat16 *ph, *pl;
            if (c < 16) {
                src = (size_t)(gk0 + r) * KV2_N + hh * NOPE + c * 8;
                ph = g_kv2_hi; pl = g_kv2_lo;
            } else {
                src = (size_t)(gk0 + r) * ROPED + (c - 16) * 8;
                ph = g_kpe_hi; pl = g_kpe_lo;
            }
            uint32_t d = (uint32_t)(r * AQS + c * 8) * 2;
            CP16(sbA + OF_KH + d, ph + src);
            CP16(sbA + OF_KL + d, pl + src);
        }
    };
    auto prefetch_V = [&](int kt) {
        const int gk0 = b * SEQ + kt * 64;
        for (int t = tid; t < 64 * 16; t += AT_THREADS) {
            int r = t / 16, c = t % 16;
            size_t src = (size_t)(gk0 + r) * KV2_N + KNOPE_DIM + hh * VDIM + c * 8;
            uint32_t d = (uint32_t)(r * AVS + c * 8) * 2;
            CP16(sbA + OF_VH + d, g_kv2_hi + src);
            CP16(sbA + OF_VL + d, g_kv2_lo + src);
        }
    };

    for (int t = tid; t < 64 * 48; t += AT_THREADS) {
        int r = t / 48, c = t % 48;
        float4 v = *(const float4*)(g_q + (size_t)(grow0 + r) * QDIM + hh * HD + c * 4);
        if (c >= 32) {
            int pos = q0 + r;
            int i0 = (c * 4 - NOPE) >> 1;
            float s0 = sin_t[pos * 32 + i0],     c0 = cos_t[pos * 32 + i0];
            float s1 = sin_t[pos * 32 + i0 + 1], c1 = cos_t[pos * 32 + i0 + 1];
            float e0 = v.x, o0 = v.y, e1 = v.z, o1 = v.w;
            v.x = e0 * c0 - o0 * s0;  v.y = e0 * s0 + o0 * c0;
            v.z = e1 * c1 - o1 * s1;  v.w = e1 * s1 + o1 * c1;
        }
        v.x *= scale; v.y *= scale; v.z *= scale; v.w *= scale;
        __align__(8) __nv_bfloat16 h[4], l[4];
        split4(v, h, l);
        *(uint2*)(sQh + r * AQS + c * 4) = *(uint2*)h;
        *(uint2*)(sQl + r * AQS + c * 4) = *(uint2*)l;
    }
    if (tid < 64) { mrow[tid] = -INFINITY; lrow[tid] = 0.f; }

    prefetch_K(0);
    prefetch_V(0);
    CP_COMMIT();

    float4 O4[8];
    #pragma unroll
    for (int k = 0; k < 8; k++) O4[k] = make_float4(0.f, 0.f, 0.f, 0.f);

    __syncthreads();

    for (int kt = 0; kt <= qt; kt++) {
        const int k0 = kt * 64;

        CP_WAIT(0);
        __syncthreads();

        {
            wmma::fragment<wmma::accumulator, 16, 16, 16, float> fs[2];
            #pragma unroll
            for (int mi = 0; mi < 2; mi++) wmma::fill_fragment(fs[mi], 0.0f);
            #pragma unroll
            for (int kk = 0; kk < HD; kk += 16) {
                wmma::fragment<wmma::matrix_a, 16, 16, 16, __nv_bfloat16, wmma::row_major> qh[2], ql[2];
                #pragma unroll
                for (int mi = 0; mi < 2; mi++) {
                    int row = warp_m * 32 + mi * 16;
                    wmma::load_matrix_sync(qh[mi], sQh + row * AQS + kk, AQS);
                    wmma::load_matrix_sync(ql[mi], sQl + row * AQS + kk, AQS);
                }
                wmma::fragment<wmma::matrix_b, 16, 16, 16, __nv_bfloat16, wmma::col_major> kh, kl;
                int col = warp_n * 16;
                wmma::load_matrix_sync(kh, sKh + col * AQS + kk, AQS);
                wmma::load_matrix_sync(kl, sKl + col * AQS + kk, AQS);
                #pragma unroll
                for (int mi = 0; mi < 2; mi++) {
                    wmma::mma_sync(fs[mi], qh[mi], kh, fs[mi]);
                    wmma::mma_sync(fs[mi], qh[mi], kl, fs[mi]);
                    wmma::mma_sync(fs[mi], ql[mi], kh, fs[mi]);
                }
            }
            #pragma unroll
            for (int mi = 0; mi < 2; mi++) {
                int row = warp_m * 32 + mi * 16;
                wmma::store_matrix_sync(sPs + row * APSTR + warp_n * 16, fs[mi],
                                        APSTR, wmma::mem_row_major);
            }
        }
        __syncthreads();

        if (kt < qt) { prefetch_K(kt + 1); CP_COMMIT(); }

        {
            int rbase = wid * 8;
            #pragma unroll
            for (int rr = 0; rr < 8; rr++) {
                int r = rbase + rr;
                int qi = q0 + r;
                float v0 = (k0 + lane      <= qi) ? sPs[r * APSTR + lane]      : -1e30f;
                float v1 = (k0 + 32 + lane <= qi) ? sPs[r * APSTR + 32 + lane] : -1e30f;
                float mx = fmaxf(v0, v1);
                #pragma unroll
                for (int o = 16; o; o >>= 1) mx = fmaxf(mx, __shfl_xor_sync(0xffffffffu, mx, o));
                float mold = mrow[r];
                float mnew = fmaxf(mold, mx);
                float p0 = __expf(v0 - mnew), p1 = __expf(v1 - mnew);
                __nv_bfloat16 h0 = __float2bfloat16(p0);
                __nv_bfloat16 h1 = __float2bfloat16(p1);
                sPh[r * APS2 + lane]      = h0;
                sPh[r * APS2 + 32 + lane] = h1;
                sPl[r * APS2 + lane]      = __float2bfloat16(p0 - __bfloat162float(h0));
                sPl[r * APS2 + 32 + lane] = __float2bfloat16(p1 - __bfloat162float(h1));
                float s = p0 + p1;
                #pragma unroll
                for (int o = 16; o; o >>= 1) s += __shfl_xor_sync(0xffffffffu, s, o);
                if (lane == 0) {
                    float a = (mold > -1e30f) ? __expf(mold - mnew) : 0.f;
                    arow[r] = a;
                    lrow[r] = lrow[r] * a + s;
                    mrow[r] = mnew;
                }
            }
        }
        __syncthreads();

        {
            wmma::fragment<wmma::accumulator, 16, 16, 16, float> fo[2][2];
            #pragma unroll
            for (int mi = 0; mi < 2; mi++)
                #pragma unroll
                for (int ni = 0; ni < 2; ni++) wmma::fill_fragment(fo[mi][ni], 0.0f);
            #pragma unroll
            for (int kk = 0; kk < 64; kk += 16) {
                wmma::fragment<wmma::matrix_a, 16, 16, 16, __nv_bfloat16, wmma::row_major> ph[2], pl[2];
                #pragma unroll
                for (int mi = 0; mi < 2; mi++) {
                    int row = warp_m * 32 + mi * 16;
                    wmma::load_matrix_sync(ph[mi], sPh + row * APS2 + kk, APS2);
                    wmma::load_matrix_sync(pl[mi], sPl + row * APS2 + kk, APS2);
                }
                #pragma unroll
                for (int ni = 0; ni < 2; ni++) {
                    int col = warp_n * 32 + ni * 16;
                    wmma::fragment<wmma::matrix_b, 16, 16, 16, __nv_bfloat16, wmma::row_major> vh, vl;
                    wmma::load_matrix_sync(vh, sVh + kk * AVS + col, AVS);
                    wmma::load_matrix_sync(vl, sVl + kk * AVS + col, AVS);
                    #pragma unroll
                    for (int mi = 0; mi < 2; mi++) {
                        wmma::mma_sync(fo[mi][ni], ph[mi], vh, fo[mi][ni]);
                        wmma::mma_sync(fo[mi][ni], ph[mi], vl, fo[mi][ni]);
                        wmma::mma_sync(fo[mi][ni], pl[mi], vh, fo[mi][ni]);
                    }
                }
            }
            #pragma unroll
            for (int mi = 0; mi < 2; mi++) {
                int row = warp_m * 32 + mi * 16;
                #pragma unroll
                for (int ni = 0; ni < 2; ni++) {
                    int col = warp_n * 32 + ni * 16;
                    wmma::store_matrix_sync(sPV + row * VDIM + col, fo[mi][ni],
                                            VDIM, wmma::mem_row_major);
                }
            }
        }
        __syncthreads();

        if (kt < qt) { prefetch_V(kt + 1); CP_COMMIT(); }

        {
            float a = arow[pr];
            #pragma unroll
            for (int k = 0; k < 8; k++) {
                float4 pv = *(float4*)(sPV + pr * VDIM + cb + 16 * k);
                O4[k].x = O4[k].x * a + pv.x;
                O4[k].y = O4[k].y * a + pv.y;
                O4[k].z = O4[k].z * a + pv.z;
                O4[k].w = O4[k].w * a + pv.w;
            }
        }
    }

    float inv = 1.f / lrow[pr];
    #pragma unroll
    for (int k = 0; k < 8; k++) {
        float4 v = make_float4(O4[k].x * inv, O4[k].y * inv, O4[k].z * inv, O4[k].w * inv);
        __align__(8) __nv_bfloat16 h[4], l[4];
        split4(v, h, l);
        size_t off = (size_t)(grow0 + pr) * VVDIM + hh * VDIM + cb + 16 * k;
        *(uint2*)(g_ao_hi + off) = *(uint2*)h;
        *(uint2*)(g_ao_lo + off) = *(uint2*)l;
    }
}

// ================= host launch =================
extern "C" void kernel_launch(void* const* d_in, const int* in_sizes, int n_in,
                              void* d_out, int out_size)
{
    const float* x        = (const float*)d_in[0];
    const float* wq_a     = (const float*)d_in[1];
    const float* w_qa_ln  = (const float*)d_in[2];
    const float* wq_b     = (const float*)d_in[3];
    const float* wkv_a    = (const float*)d_in[4];
    const float* w_kva_ln = (const float*)d_in[5];
    const float* wk_b     = (const float*)d_in[6];
    const float* wv_b     = (const float*)d_in[7];
    const float* wo       = (const float*)d_in[8];
    const float* rsin     = (const float*)d_in[9];
    const float* rcos     = (const float*)d_in[10];
    float* out = (float*)d_out;

    float *qakv, *q;
    cudaGetSymbolAddress((void**)&qakv, g_qakv);
    cudaGetSymbolAddress((void**)&q,    g_q);

    __nv_bfloat16 *xh, *xl, *qnh, *qnl, *ckvh, *ckvl, *aoh, *aol, *kv2h, *kv2l;
    __nv_bfloat16 *w1h, *w1l, *wqbh, *wqbl, *w2h, *w2l, *woh, *wol;
    cudaGetSymbolAddress((void**)&xh,   g_x_hi);   cudaGetSymbolAddress((void**)&xl,   g_x_lo);
    cudaGetSymbolAddress((void**)&qnh,  g_qn_hi);  cudaGetSymbolAddress((void**)&qnl,  g_qn_lo);
    cudaGetSymbolAddress((void**)&ckvh, g_ckv_hi); cudaGetSymbolAddress((void**)&ckvl, g_ckv_lo);
    cudaGetSymbolAddress((void**)&aoh,  g_ao_hi);  cudaGetSymbolAddress((void**)&aol,  g_ao_lo);
    cudaGetSymbolAddress((void**)&kv2h, g_kv2_hi); cudaGetSymbolAddress((void**)&kv2l, g_kv2_lo);
    cudaGetSymbolAddress((void**)&w1h,  g_w1_hi);  cudaGetSymbolAddress((void**)&w1l,  g_w1_lo);
    cudaGetSymbolAddress((void**)&wqbh, g_wqb_hi); cudaGetSymbolAddress((void**)&wqbl, g_wqb_lo);
    cudaGetSymbolAddress((void**)&w2h,  g_w2_hi);  cudaGetSymbolAddress((void**)&w2l,  g_w2_lo);
    cudaGetSymbolAddress((void**)&woh,  g_wo_hi);  cudaGetSymbolAddress((void**)&wol,  g_wo_lo);

    cudaFuncSetAttribute(gemm_wmma, cudaFuncAttributeMaxDynamicSharedMemorySize, GEMM_SMEM);
    cudaFuncSetAttribute(gemm_dual, cudaFuncAttributeMaxDynamicSharedMemorySize, GEMM_SMEM);
    cudaFuncSetAttribute(attn_k,    cudaFuncAttributeMaxDynamicSharedMemorySize, ATT_SMEM);

    SplitSegs segs;
    segs.s[0] = x;     segs.h[0] = xh;   segs.l[0] = xl;
    segs.s[1] = wq_a;  segs.h[1] = w1h;  segs.l[1] = w1l;
    segs.s[2] = wkv_a; segs.h[2] = w1h + (size_t)QLR * HIDDIM;
                       segs.l[2] = w1l + (size_t)QLR * HIDDIM;
    segs.s[3] = wq_b;  segs.h[3] = wqbh; segs.l[3] = wqbl;
    segs.s[4] = wk_b;  segs.h[4] = w2h;  segs.l[4] = w2l;
    segs.s[5] = wv_b;  segs.h[5] = w2h + (size_t)KNOPE_DIM * KVLR;
                       segs.l[5] = w2l + (size_t)KNOPE_DIM * KVLR;
    segs.s[6] = wo;    segs.h[6] = woh;  segs.l[6] = wol;
    split_all_k<<<(unsigned)((SEG_VECS + 255) / 256), 256>>>(segs);

    gemm_wmma<<<dim3(QAKV_N / GBN, NTOK / GBM), 256, GEMM_SMEM>>>(
        xh, xl, w1h, w1l, qakv, QAKV_N, QAKV_V, HIDDIM);

    norms_k<<<NTOK, 256>>>(w_qa_ln, w_kva_ln, rsin, rcos);

    gemm_dual<<<DG_T1 + DG_T2, 256, GEMM_SMEM>>>(
        qnh, qnl, wqbh, wqbl, q,
        ckvh, ckvl, w2h, w2l, kv2h, kv2l);

    attn_k<<<dim3(SEQ / 64, HEADS, BATCH), AT_THREADS, ATT_SMEM>>>(rsin, rcos);

    gemm_wmma<<<dim3(HIDDIM / GBN, NTOK / GBM), 256, GEMM_SMEM>>>(
        aoh, aol, woh, wol, out, HIDDIM, HIDDIM, VVDIM);
}